// round 13
// baseline (speedup 1.0000x reference)
#include <cuda_runtime.h>
#include <cuda_fp16.h>
#include <cstdint>

#define NROW 1024
#define KDIM 2048
#define NF   128
#define SPLITK 8
#define KCHUNK (KDIM / SPLITK)   // 256
#define BK 64

// ---------------------------------------------------------------------------
// Device scratch
// ---------------------------------------------------------------------------
__device__ __half g_fh[NF * KDIM];               // feats fp16 (prep output)
__device__ __half g_ph[SPLITK * 2048 * NF];      // fp16 split-K partials
__device__ __half g_shi[2048 * NF];              // relu(scores) fp16, [m][k]

// ---------------------------------------------------------------------------
// Helpers
// ---------------------------------------------------------------------------
__device__ __forceinline__ uint32_t su32(const void* p) {
    return (uint32_t)__cvta_generic_to_shared(p);
}
__device__ __forceinline__ uint32_t pk(__half a, __half b) {
    __half2 h = __halves2half2(a, b);
    return *reinterpret_cast<uint32_t*>(&h);
}
__device__ __forceinline__ void cp16(uint32_t dst, const void* src) {
    asm volatile("cp.async.ca.shared.global [%0], [%1], 16;" :: "r"(dst), "l"(src));
}

#define CP_COMMIT() asm volatile("cp.async.commit_group;" ::: "memory")
#define CP_WAIT0()  asm volatile("cp.async.wait_group 0;"  ::: "memory")
#define CP_WAIT1()  asm volatile("cp.async.wait_group 1;"  ::: "memory")

#define LDSM4(R, addr) \
    asm volatile("ldmatrix.sync.aligned.m8n8.x4.shared.b16 {%0,%1,%2,%3}, [%4];" \
        : "=r"((R)[0]), "=r"((R)[1]), "=r"((R)[2]), "=r"((R)[3]) : "r"(addr))

#define MMA(C, A, b0, b1) \
    asm volatile("mma.sync.aligned.m16n8k16.row.col.f32.f16.f16.f32 " \
        "{%0,%1,%2,%3}, {%4,%5,%6,%7}, {%8,%9}, {%0,%1,%2,%3};" \
        : "+f"((C)[0]), "+f"((C)[1]), "+f"((C)[2]), "+f"((C)[3]) \
        : "r"((A)[0]), "r"((A)[1]), "r"((A)[2]), "r"((A)[3]), "r"(b0), "r"(b1))

// swizzled byte offset, 128B rows (64 halves)
__device__ __forceinline__ uint32_t swz1(int row, int kh) {
    return (uint32_t)(row * 128 + ((((kh >> 3) ^ (row & 7)) << 4)));
}
// swizzled byte offset, 256B rows (128 halves)
__device__ __forceinline__ uint32_t swz2(int row, int kh) {
    int c = kh >> 3;
    return (uint32_t)(row * 256 + ((((c & 8) | ((c ^ (row & 7)) & 7)) << 4)));
}

__device__ __forceinline__ uint2 round4(float4 v) {
    uint2 hw;
    hw.x = pk(__float2half_rn(v.x), __float2half_rn(v.y));
    hw.y = pk(__float2half_rn(v.z), __float2half_rn(v.w));
    return hw;
}

// ---------------------------------------------------------------------------
// Prep: feats fp32 -> fp16 (row-major [NF][KDIM])
// ---------------------------------------------------------------------------
__global__ void prep_feats(const float* __restrict__ f) {
    int g = blockIdx.x * blockDim.x + threadIdx.x;   // 32768 threads
    size_t base = (size_t)g * 8;                     // 256K elements
    *(uint2*)&g_fh[base]     = round4(*(const float4*)&f[base]);
    *(uint2*)&g_fh[base + 4] = round4(*(const float4*)&f[base + 4]);
}

// ---------------------------------------------------------------------------
// Stage 1: partial[ks][m 64-tile][0..127] = X[m, kchunk] . feats^T (fp16 MMA)
// grid (32 m, 8 ks) = 256 CTAs (~2/SM), 256 threads (8 warps, warp 32m x 32n).
// X converted inline; F fetched fp16 via cp.async from g_fh.
// smem per buffer (24576B): X +0 (8KB), F +8192 (16KB); two buffers = 48KB.
// ---------------------------------------------------------------------------
__global__ __launch_bounds__(256, 2) void stage1(const float* __restrict__ A_,
                                                 const float* __restrict__ B_) {
    extern __shared__ char smem[];
    const int t = threadIdx.x, lane = t & 31, wid = t >> 5;
    const uint32_t sb = su32(smem);
    const int m0 = blockIdx.x * 64;
    const int ks = blockIdx.y;
    const float* X = (m0 < NROW) ? A_ : B_;
    const int mb = (m0 < NROW) ? m0 : m0 - NROW;
    const int kbase = ks * KCHUNK;

    const int wy = wid & 1, wx = wid >> 1;
    const int m0w = wy * 32, n0w = wx * 32;
    const int aRow = lane & 15, aK = (lane >> 4) << 3;
    const int bN = ((lane >> 4) << 3) + (lane & 7), bK = ((lane >> 3) & 1) << 3;

    float acc[2][4][4];
    #pragma unroll
    for (int i = 0; i < 2; i++)
        #pragma unroll
        for (int j = 0; j < 4; j++)
            #pragma unroll
            for (int q = 0; q < 4; q++) acc[i][j][q] = 0.f;

    // X load mapping: 64 rows x 8 chunks = 512 chunks / 256 thr = 2 each
    int xrow[2], xc[2];
    #pragma unroll
    for (int i = 0; i < 2; i++) {
        int idx = t + i * 256;
        xrow[i] = idx >> 3;
        xc[i]   = idx & 7;
    }
    // F cp.async mapping: 128 rows x 8 chunks = 1024 chunks / 256 thr = 4 each
    int frow[4], fc[4];
    #pragma unroll
    for (int i = 0; i < 4; i++) {
        int idx = t + i * 256;
        frow[i] = idx >> 3;
        fc[i]   = idx & 7;
    }

    float xr[2][8];

    // ---- slab 0 prologue ----
    {
        const int kk = kbase;
        #pragma unroll
        for (int i = 0; i < 4; i++) {
            uint32_t off = swz1(frow[i], fc[i] * 8);
            cp16(sb + 8192 + off, &g_fh[(size_t)frow[i] * KDIM + kk + fc[i] * 8]);
        }
        CP_COMMIT();
        #pragma unroll
        for (int i = 0; i < 2; i++) {
            const float* sx = &X[(size_t)(mb + xrow[i]) * KDIM + kk + xc[i] * 8];
            *(float4*)&xr[i][0] = *(const float4*)sx;
            *(float4*)&xr[i][4] = *(const float4*)(sx + 4);
        }
        #pragma unroll
        for (int i = 0; i < 2; i++) {
            uint32_t off = swz1(xrow[i], xc[i] * 8);
            uint2 x0 = round4(*(float4*)&xr[i][0]);
            uint2 x1 = round4(*(float4*)&xr[i][4]);
            *(uint4*)(smem + off) = make_uint4(x0.x, x0.y, x1.x, x1.y);
        }
        CP_WAIT0();
        __syncthreads();
    }

    // ---- main loop over 4 slabs ----
    #pragma unroll 1
    for (int s = 0; s < 4; s++) {
        const int p = s & 1, np = p ^ 1;
        if (s < 3) {
            const int kk = kbase + (s + 1) * BK;
            const uint32_t nb = sb + np * 24576;
            #pragma unroll
            for (int i = 0; i < 4; i++) {
                uint32_t off = swz1(frow[i], fc[i] * 8);
                cp16(nb + 8192 + off, &g_fh[(size_t)frow[i] * KDIM + kk + fc[i] * 8]);
            }
            CP_COMMIT();
            #pragma unroll
            for (int i = 0; i < 2; i++) {
                const float* sx = &X[(size_t)(mb + xrow[i]) * KDIM + kk + xc[i] * 8];
                *(float4*)&xr[i][0] = *(const float4*)sx;
                *(float4*)&xr[i][4] = *(const float4*)(sx + 4);
            }
        }

        const uint32_t base = sb + p * 24576;
        #pragma unroll
        for (int k16 = 0; k16 < 4; k16++) {
            const int kh = k16 * 16;
            uint32_t ah[2][4], bh[2][4];
            #pragma unroll
            for (int mt = 0; mt < 2; mt++) {
                uint32_t ra = base + swz1(m0w + mt * 16 + aRow, kh + aK);
                LDSM4(ah[mt], ra);
            }
            #pragma unroll
            for (int g = 0; g < 2; g++) {
                uint32_t rb = base + 8192 + swz1(n0w + g * 16 + bN, kh + bK);
                LDSM4(bh[g], rb);
            }
            #pragma unroll
            for (int mt = 0; mt < 2; mt++)
                #pragma unroll
                for (int nt = 0; nt < 4; nt++) {
                    uint32_t h0 = bh[nt >> 1][(nt & 1) * 2], h1 = bh[nt >> 1][(nt & 1) * 2 + 1];
                    MMA(acc[mt][nt], ah[mt], h0, h1);
                }
        }

        if (s < 3) {
            const uint32_t nboff = (uint32_t)(np * 24576);
            #pragma unroll
            for (int i = 0; i < 2; i++) {
                uint32_t off = nboff + swz1(xrow[i], xc[i] * 8);
                uint2 x0 = round4(*(float4*)&xr[i][0]);
                uint2 x1 = round4(*(float4*)&xr[i][4]);
                *(uint4*)(smem + off) = make_uint4(x0.x, x0.y, x1.x, x1.y);
            }
            CP_WAIT0();
        }
        __syncthreads();
    }

    // ---- epilogue: write fp16 partials ----
    __half* dst = g_ph + (size_t)ks * (2048 * NF);
    #pragma unroll
    for (int mt = 0; mt < 2; mt++)
        #pragma unroll
        for (int nt = 0; nt < 4; nt++) {
            int r = m0 + m0w + mt * 16 + (lane >> 2);
            int cc = n0w + nt * 8 + (lane & 3) * 2;
            *(uint32_t*)&dst[(size_t)r * NF + cc] =
                pk(__float2half_rn(acc[mt][nt][0]), __float2half_rn(acc[mt][nt][1]));
            *(uint32_t*)&dst[(size_t)(r + 8) * NF + cc] =
                pk(__float2half_rn(acc[mt][nt][2]), __float2half_rn(acc[mt][nt][3]));
        }
}

// ---------------------------------------------------------------------------
// Reduce: sum fp16 split-K partials in fp32, relu, round to fp16
// ---------------------------------------------------------------------------
__global__ void reduce_relu() {
    int g = blockIdx.x * blockDim.x + threadIdx.x;   // 65536 threads
    size_t o = (size_t)g * 4;
    float4 s = make_float4(0.f, 0.f, 0.f, 0.f);
    #pragma unroll
    for (int p = 0; p < SPLITK; p++) {
        uint2 v = *(const uint2*)&g_ph[(size_t)p * (2048 * NF) + o];
        __half2 h0 = *reinterpret_cast<__half2*>(&v.x);
        __half2 h1 = *reinterpret_cast<__half2*>(&v.y);
        float2 f0 = __half22float2(h0);
        float2 f1 = __half22float2(h1);
        s.x += f0.x; s.y += f0.y; s.z += f1.x; s.w += f1.y;
    }
    s.x = fmaxf(s.x, 0.f); s.y = fmaxf(s.y, 0.f);
    s.z = fmaxf(s.z, 0.f); s.w = fmaxf(s.w, 0.f);
    *(uint2*)&g_shi[o] = round4(s);
}

// ---------------------------------------------------------------------------
// Stage 2: out[i][j] = sum_k shi[i][k] * shi[1024+j][k]
// grid (16 j, 8 i): CTA 128i x 64j, 512 threads (warp tile 32i x 16j).
// smem: AHI +0 (32KB), BHI +32768 (16KB) = 48KB, cp.async 2 K-half groups.
// ---------------------------------------------------------------------------
__global__ __launch_bounds__(512, 1) void stage2(float* __restrict__ out) {
    extern __shared__ char smem[];
    const uint32_t sb = su32(smem);
    const int t = threadIdx.x, lane = t & 31, wid = t >> 5;
    const int it = blockIdx.y * 128, jt = blockIdx.x * 64;
    const int wy = wid & 3, wx = wid >> 2;
    const int m0w = wy * 32, n0w = wx * 16;

    // two K-half commit groups: group cc covers kh [cc*64, cc*64+64)
    #pragma unroll
    for (int cc = 0; cc < 2; cc++) {
        #pragma unroll
        for (int i = 0; i < 2; i++) {
            int idx = t + i * 512;                 // 0..1023
            int row = idx >> 3, c = (idx & 7) + cc * 8;
            uint32_t off = swz2(row, c * 8);
            cp16(sb + off, &g_shi[(size_t)(it + row) * NF + c * 8]);
        }
        {
            int row = t >> 3, c = (t & 7) + cc * 8;   // 512 -> 64 rows
            uint32_t off = swz2(row, c * 8);
            cp16(sb + 32768 + off, &g_shi[(size_t)(1024 + jt + row) * NF + c * 8]);
        }
        CP_COMMIT();
    }

    const int aRow = lane & 15, aK = (lane >> 4) << 3;
    const int bN = ((lane >> 4) << 3) + (lane & 7), bK = ((lane >> 3) & 1) << 3;

    float acc[2][2][4];
    #pragma unroll
    for (int i = 0; i < 2; i++)
        #pragma unroll
        for (int j = 0; j < 2; j++)
            #pragma unroll
            for (int q = 0; q < 4; q++) acc[i][j][q] = 0.f;

    CP_WAIT1();
    __syncthreads();

    #pragma unroll
    for (int half = 0; half < 2; half++) {
        #pragma unroll
        for (int k16 = 0; k16 < 4; k16++) {
            const int kh = half * 64 + k16 * 16;
            uint32_t ah[2][4], bh[4];
            #pragma unroll
            for (int mt = 0; mt < 2; mt++) {
                uint32_t ra = sb + swz2(m0w + mt * 16 + aRow, kh + aK);
                LDSM4(ah[mt], ra);
            }
            {
                uint32_t rb = sb + 32768 + swz2(n0w + bN, kh + bK);
                LDSM4(bh, rb);
            }
            #pragma unroll
            for (int mt = 0; mt < 2; mt++)
                #pragma unroll
                for (int nt = 0; nt < 2; nt++) {
                    uint32_t h0 = bh[nt * 2], h1 = bh[nt * 2 + 1];
                    MMA(acc[mt][nt], ah[mt], h0, h1);
                }
        }
        if (half == 0) {
            CP_WAIT0();
            __syncthreads();
        }
    }

    #pragma unroll
    for (int mt = 0; mt < 2; mt++)
        #pragma unroll
        for (int nt = 0; nt < 2; nt++) {
            int r = it + m0w + mt * 16 + (lane >> 2);
            int cc = jt + n0w + nt * 8 + (lane & 3) * 2;
            *(float2*)&out[(size_t)r * NROW + cc] =
                make_float2(acc[mt][nt][0], acc[mt][nt][1]);
            *(float2*)&out[(size_t)(r + 8) * NROW + cc] =
                make_float2(acc[mt][nt][2], acc[mt][nt][3]);
        }
}

// ---------------------------------------------------------------------------
extern "C" void kernel_launch(void* const* d_in, const int* in_sizes, int n_in,
                              void* d_out, int out_size) {
    (void)in_sizes; (void)n_in; (void)out_size;
    const float* a = (const float*)d_in[0];
    const float* b = (const float*)d_in[1];
    const float* f = (const float*)d_in[2];
    float* out = (float*)d_out;

    cudaFuncSetAttribute(stage1, cudaFuncAttributeMaxDynamicSharedMemorySize, 49152);
    cudaFuncSetAttribute(stage2, cudaFuncAttributeMaxDynamicSharedMemorySize, 49152);

    prep_feats<<<128, 256>>>(f);
    stage1<<<dim3(32, SPLITK), 256, 49152>>>(a, b);
    reduce_relu<<<256, 256>>>();
    stage2<<<dim3(16, 8), 512, 49152>>>(out);
}

// round 14
// speedup vs baseline: 1.0649x; 1.0649x over previous
#include <cuda_runtime.h>
#include <cuda_fp16.h>
#include <cstdint>

#define NROW 1024
#define KDIM 2048
#define NF   128
#define SPLITK 8
#define KCHUNK (KDIM / SPLITK)   // 256
#define BK 64

// ---------------------------------------------------------------------------
// Device scratch
// ---------------------------------------------------------------------------
__device__ __half g_fh[NF * KDIM];               // feats fp16 (prep output)
__device__ __half g_ph[SPLITK * 2048 * NF];      // fp16 split-K partials
__device__ __half g_shi[2048 * NF];              // relu(scores) fp16, [m][k]

// ---------------------------------------------------------------------------
// Helpers
// ---------------------------------------------------------------------------
__device__ __forceinline__ uint32_t su32(const void* p) {
    return (uint32_t)__cvta_generic_to_shared(p);
}
__device__ __forceinline__ uint32_t pk2(float a, float b) {
    __half2 h = __floats2half2_rn(a, b);          // cvt.rn.f16x2.f32 (packed)
    return *reinterpret_cast<uint32_t*>(&h);
}
__device__ __forceinline__ void cp16(uint32_t dst, const void* src) {
    asm volatile("cp.async.ca.shared.global [%0], [%1], 16;" :: "r"(dst), "l"(src));
}

#define CP_COMMIT() asm volatile("cp.async.commit_group;" ::: "memory")
#define CP_WAIT0()  asm volatile("cp.async.wait_group 0;"  ::: "memory")
#define CP_WAIT1()  asm volatile("cp.async.wait_group 1;"  ::: "memory")

#define LDSM4(R, addr) \
    asm volatile("ldmatrix.sync.aligned.m8n8.x4.shared.b16 {%0,%1,%2,%3}, [%4];" \
        : "=r"((R)[0]), "=r"((R)[1]), "=r"((R)[2]), "=r"((R)[3]) : "r"(addr))

#define MMA(C, A, b0, b1) \
    asm volatile("mma.sync.aligned.m16n8k16.row.col.f32.f16.f16.f32 " \
        "{%0,%1,%2,%3}, {%4,%5,%6,%7}, {%8,%9}, {%0,%1,%2,%3};" \
        : "+f"((C)[0]), "+f"((C)[1]), "+f"((C)[2]), "+f"((C)[3]) \
        : "r"((A)[0]), "r"((A)[1]), "r"((A)[2]), "r"((A)[3]), "r"(b0), "r"(b1))

// swizzled byte offset, 128B rows (64 halves)
__device__ __forceinline__ uint32_t swz1(int row, int kh) {
    return (uint32_t)(row * 128 + ((((kh >> 3) ^ (row & 7)) << 4)));
}
// swizzled byte offset, 256B rows (128 halves)
__device__ __forceinline__ uint32_t swz2(int row, int kh) {
    int c = kh >> 3;
    return (uint32_t)(row * 256 + ((((c & 8) | ((c ^ (row & 7)) & 7)) << 4)));
}

__device__ __forceinline__ uint2 round4(float4 v) {
    uint2 hw;
    hw.x = pk2(v.x, v.y);
    hw.y = pk2(v.z, v.w);
    return hw;
}

// ---------------------------------------------------------------------------
// Prep: feats fp32 -> fp16 (row-major [NF][KDIM])
// ---------------------------------------------------------------------------
__global__ void prep_feats(const float* __restrict__ f) {
    int g = blockIdx.x * blockDim.x + threadIdx.x;   // 32768 threads
    size_t base = (size_t)g * 8;                     // 256K elements
    *(uint2*)&g_fh[base]     = round4(*(const float4*)&f[base]);
    *(uint2*)&g_fh[base + 4] = round4(*(const float4*)&f[base + 4]);
}

// ---------------------------------------------------------------------------
// Stage 1: partial[ks][m 128-tile][0..127] = X[m, kchunk] . feats^T (fp16 MMA)
// grid (16 m, 8 ks), 512 threads (16 warps, warp tile 32m x 32n).
// X converted inline (packed cvt); F fetched fp16 via cp.async from g_fh.
// smem per buffer (32768B): X +0 (16KB), F +16384 (16KB); two buffers = 64KB.
// Epilogue: fp16 partials.
// ---------------------------------------------------------------------------
__global__ __launch_bounds__(512, 1) void stage1(const float* __restrict__ A_,
                                                 const float* __restrict__ B_) {
    extern __shared__ char smem[];
    const int t = threadIdx.x, lane = t & 31, wid = t >> 5;
    const uint32_t sb = su32(smem);
    const int m0 = blockIdx.x * 128;
    const int ks = blockIdx.y;
    const float* X = (m0 < NROW) ? A_ : B_;
    const int mb = (m0 < NROW) ? m0 : m0 - NROW;
    const int kbase = ks * KCHUNK;

    const int wy = wid & 3, wx = wid >> 2;
    const int m0w = wy * 32, n0w = wx * 32;
    const int aRow = lane & 15, aK = (lane >> 4) << 3;
    const int bN = ((lane >> 4) << 3) + (lane & 7), bK = ((lane >> 3) & 1) << 3;

    float acc[2][4][4];
    #pragma unroll
    for (int i = 0; i < 2; i++)
        #pragma unroll
        for (int j = 0; j < 4; j++)
            #pragma unroll
            for (int q = 0; q < 4; q++) acc[i][j][q] = 0.f;

    // X/F tile coords: 128 rows x 8 chunks = 1024 units / 512 thr = 2 each
    int rows_[2], cs_[2];
    #pragma unroll
    for (int i = 0; i < 2; i++) {
        int idx = t + i * 512;
        rows_[i] = idx >> 3;
        cs_[i]   = idx & 7;
    }

    float xr[2][8];

    // ---- slab 0 prologue ----
    {
        const int kk = kbase;
        #pragma unroll
        for (int i = 0; i < 2; i++) {
            uint32_t off = swz1(rows_[i], cs_[i] * 8);
            cp16(sb + 16384 + off, &g_fh[(size_t)rows_[i] * KDIM + kk + cs_[i] * 8]);
        }
        CP_COMMIT();
        #pragma unroll
        for (int i = 0; i < 2; i++) {
            const float* sx = &X[(size_t)(mb + rows_[i]) * KDIM + kk + cs_[i] * 8];
            *(float4*)&xr[i][0] = *(const float4*)sx;
            *(float4*)&xr[i][4] = *(const float4*)(sx + 4);
        }
        #pragma unroll
        for (int i = 0; i < 2; i++) {
            uint32_t off = swz1(rows_[i], cs_[i] * 8);
            uint2 x0 = round4(*(float4*)&xr[i][0]);
            uint2 x1 = round4(*(float4*)&xr[i][4]);
            *(uint4*)(smem + off) = make_uint4(x0.x, x0.y, x1.x, x1.y);
        }
        CP_WAIT0();
        __syncthreads();
    }

    // ---- main loop over 4 slabs ----
    #pragma unroll 1
    for (int s = 0; s < 4; s++) {
        const int p = s & 1, np = p ^ 1;
        if (s < 3) {
            const int kk = kbase + (s + 1) * BK;
            const uint32_t nb = sb + np * 32768;
            #pragma unroll
            for (int i = 0; i < 2; i++) {
                uint32_t off = swz1(rows_[i], cs_[i] * 8);
                cp16(nb + 16384 + off, &g_fh[(size_t)rows_[i] * KDIM + kk + cs_[i] * 8]);
            }
            CP_COMMIT();
            #pragma unroll
            for (int i = 0; i < 2; i++) {
                const float* sx = &X[(size_t)(mb + rows_[i]) * KDIM + kk + cs_[i] * 8];
                *(float4*)&xr[i][0] = *(const float4*)sx;
                *(float4*)&xr[i][4] = *(const float4*)(sx + 4);
            }
        }

        const uint32_t base = sb + p * 32768;
        #pragma unroll
        for (int k16 = 0; k16 < 4; k16++) {
            const int kh = k16 * 16;
            uint32_t ah[2][4], bh[2][4];
            #pragma unroll
            for (int mt = 0; mt < 2; mt++) {
                uint32_t ra = base + swz1(m0w + mt * 16 + aRow, kh + aK);
                LDSM4(ah[mt], ra);
            }
            #pragma unroll
            for (int g = 0; g < 2; g++) {
                uint32_t rb = base + 16384 + swz1(n0w + g * 16 + bN, kh + bK);
                LDSM4(bh[g], rb);
            }
            #pragma unroll
            for (int mt = 0; mt < 2; mt++)
                #pragma unroll
                for (int nt = 0; nt < 4; nt++) {
                    uint32_t h0 = bh[nt >> 1][(nt & 1) * 2], h1 = bh[nt >> 1][(nt & 1) * 2 + 1];
                    MMA(acc[mt][nt], ah[mt], h0, h1);
                }
        }

        if (s < 3) {
            const uint32_t nboff = (uint32_t)(np * 32768);
            #pragma unroll
            for (int i = 0; i < 2; i++) {
                uint32_t off = nboff + swz1(rows_[i], cs_[i] * 8);
                uint2 x0 = round4(*(float4*)&xr[i][0]);
                uint2 x1 = round4(*(float4*)&xr[i][4]);
                *(uint4*)(smem + off) = make_uint4(x0.x, x0.y, x1.x, x1.y);
            }
            CP_WAIT0();
        }
        __syncthreads();
    }

    // ---- epilogue: write fp16 partials ----
    __half* dst = g_ph + (size_t)ks * (2048 * NF);
    #pragma unroll
    for (int mt = 0; mt < 2; mt++)
        #pragma unroll
        for (int nt = 0; nt < 4; nt++) {
            int r = m0 + m0w + mt * 16 + (lane >> 2);
            int cc = n0w + nt * 8 + (lane & 3) * 2;
            *(uint32_t*)&dst[(size_t)r * NF + cc] =
                pk2(acc[mt][nt][0], acc[mt][nt][1]);
            *(uint32_t*)&dst[(size_t)(r + 8) * NF + cc] =
                pk2(acc[mt][nt][2], acc[mt][nt][3]);
        }
}

// ---------------------------------------------------------------------------
// Reduce: sum fp16 split-K partials in fp32, relu, round to fp16
// ---------------------------------------------------------------------------
__global__ void reduce_relu() {
    int g = blockIdx.x * blockDim.x + threadIdx.x;   // 65536 threads
    size_t o = (size_t)g * 4;
    float4 s = make_float4(0.f, 0.f, 0.f, 0.f);
    #pragma unroll
    for (int p = 0; p < SPLITK; p++) {
        uint2 v = *(const uint2*)&g_ph[(size_t)p * (2048 * NF) + o];
        __half2 h0 = *reinterpret_cast<__half2*>(&v.x);
        __half2 h1 = *reinterpret_cast<__half2*>(&v.y);
        float2 f0 = __half22float2(h0);
        float2 f1 = __half22float2(h1);
        s.x += f0.x; s.y += f0.y; s.z += f1.x; s.w += f1.y;
    }
    s.x = fmaxf(s.x, 0.f); s.y = fmaxf(s.y, 0.f);
    s.z = fmaxf(s.z, 0.f); s.w = fmaxf(s.w, 0.f);
    *(uint2*)&g_shi[o] = round4(s);
}

// ---------------------------------------------------------------------------
// Stage 2: out[i][j] = sum_k shi[i][k] * shi[1024+j][k]
// grid (16 j, 8 i): CTA 128i x 64j, 512 threads (warp tile 32i x 16j).
// smem: AHI +0 (32KB), BHI +32768 (16KB) = 48KB, cp.async 2 K-half groups.
// ---------------------------------------------------------------------------
__global__ __launch_bounds__(512, 1) void stage2(float* __restrict__ out) {
    extern __shared__ char smem[];
    const uint32_t sb = su32(smem);
    const int t = threadIdx.x, lane = t & 31, wid = t >> 5;
    const int it = blockIdx.y * 128, jt = blockIdx.x * 64;
    const int wy = wid & 3, wx = wid >> 2;
    const int m0w = wy * 32, n0w = wx * 16;

    // two K-half commit groups: group cc covers kh [cc*64, cc*64+64)
    #pragma unroll
    for (int cc = 0; cc < 2; cc++) {
        #pragma unroll
        for (int i = 0; i < 2; i++) {
            int idx = t + i * 512;                 // 0..1023
            int row = idx >> 3, c = (idx & 7) + cc * 8;
            uint32_t off = swz2(row, c * 8);
            cp16(sb + off, &g_shi[(size_t)(it + row) * NF + c * 8]);
        }
        {
            int row = t >> 3, c = (t & 7) + cc * 8;   // 512 -> 64 rows
            uint32_t off = swz2(row, c * 8);
            cp16(sb + 32768 + off, &g_shi[(size_t)(1024 + jt + row) * NF + c * 8]);
        }
        CP_COMMIT();
    }

    const int aRow = lane & 15, aK = (lane >> 4) << 3;
    const int bN = ((lane >> 4) << 3) + (lane & 7), bK = ((lane >> 3) & 1) << 3;

    float acc[2][2][4];
    #pragma unroll
    for (int i = 0; i < 2; i++)
        #pragma unroll
        for (int j = 0; j < 2; j++)
            #pragma unroll
            for (int q = 0; q < 4; q++) acc[i][j][q] = 0.f;

    CP_WAIT1();
    __syncthreads();

    #pragma unroll
    for (int half = 0; half < 2; half++) {
        #pragma unroll
        for (int k16 = 0; k16 < 4; k16++) {
            const int kh = half * 64 + k16 * 16;
            uint32_t ah[2][4], bh[4];
            #pragma unroll
            for (int mt = 0; mt < 2; mt++) {
                uint32_t ra = sb + swz2(m0w + mt * 16 + aRow, kh + aK);
                LDSM4(ah[mt], ra);
            }
            {
                uint32_t rb = sb + 32768 + swz2(n0w + bN, kh + bK);
                LDSM4(bh, rb);
            }
            #pragma unroll
            for (int mt = 0; mt < 2; mt++)
                #pragma unroll
                for (int nt = 0; nt < 2; nt++) {
                    uint32_t h0 = bh[nt * 2], h1 = bh[nt * 2 + 1];
                    MMA(acc[mt][nt], ah[mt], h0, h1);
                }
        }
        if (half == 0) {
            CP_WAIT0();
            __syncthreads();
        }
    }

    #pragma unroll
    for (int mt = 0; mt < 2; mt++)
        #pragma unroll
        for (int nt = 0; nt < 2; nt++) {
            int r = it + m0w + mt * 16 + (lane >> 2);
            int cc = jt + n0w + nt * 8 + (lane & 3) * 2;
            *(float2*)&out[(size_t)r * NROW + cc] =
                make_float2(acc[mt][nt][0], acc[mt][nt][1]);
            *(float2*)&out[(size_t)(r + 8) * NROW + cc] =
                make_float2(acc[mt][nt][2], acc[mt][nt][3]);
        }
}

// ---------------------------------------------------------------------------
extern "C" void kernel_launch(void* const* d_in, const int* in_sizes, int n_in,
                              void* d_out, int out_size) {
    (void)in_sizes; (void)n_in; (void)out_size;
    const float* a = (const float*)d_in[0];
    const float* b = (const float*)d_in[1];
    const float* f = (const float*)d_in[2];
    float* out = (float*)d_out;

    cudaFuncSetAttribute(stage1, cudaFuncAttributeMaxDynamicSharedMemorySize, 65536);
    cudaFuncSetAttribute(stage2, cudaFuncAttributeMaxDynamicSharedMemorySize, 49152);

    prep_feats<<<128, 256>>>(f);
    stage1<<<dim3(16, SPLITK), 512, 65536>>>(a, b);
    reduce_relu<<<256, 256>>>();
    stage2<<<dim3(16, 8), 512, 49152>>>(out);
}

// round 15
// speedup vs baseline: 1.1047x; 1.0374x over previous
#include <cuda_runtime.h>
#include <cuda_fp16.h>
#include <cstdint>

#define NROW 1024
#define KDIM 2048
#define NF   128
#define SPLITK 8
#define KCHUNK (KDIM / SPLITK)   // 256
#define BK 64

// ---------------------------------------------------------------------------
// Device scratch
// ---------------------------------------------------------------------------
__device__ __half g_ph[SPLITK * 2048 * NF];      // fp16 split-K partials [ks][m][n]
__device__ __half g_shi[2048 * NF];              // relu(scores) fp16, [m][k]

// ---------------------------------------------------------------------------
// Helpers
// ---------------------------------------------------------------------------
__device__ __forceinline__ uint32_t su32(const void* p) {
    return (uint32_t)__cvta_generic_to_shared(p);
}
__device__ __forceinline__ uint32_t pk2(float a, float b) {
    __half2 h = __floats2half2_rn(a, b);          // packed cvt.rn.f16x2.f32
    return *reinterpret_cast<uint32_t*>(&h);
}
__device__ __forceinline__ void cp16(uint32_t dst, const void* src) {
    asm volatile("cp.async.ca.shared.global [%0], [%1], 16;" :: "r"(dst), "l"(src));
}
__device__ __forceinline__ void gdc_wait() {
    asm volatile("griddepcontrol.wait;" ::: "memory");
}
__device__ __forceinline__ void gdc_launch() {
    asm volatile("griddepcontrol.launch_dependents;");
}

#define CP_COMMIT() asm volatile("cp.async.commit_group;" ::: "memory")
#define CP_WAIT0()  asm volatile("cp.async.wait_group 0;"  ::: "memory")
#define CP_WAIT1()  asm volatile("cp.async.wait_group 1;"  ::: "memory")

#define LDSM4(R, addr) \
    asm volatile("ldmatrix.sync.aligned.m8n8.x4.shared.b16 {%0,%1,%2,%3}, [%4];" \
        : "=r"((R)[0]), "=r"((R)[1]), "=r"((R)[2]), "=r"((R)[3]) : "r"(addr))

#define MMA(C, A, b0, b1) \
    asm volatile("mma.sync.aligned.m16n8k16.row.col.f32.f16.f16.f32 " \
        "{%0,%1,%2,%3}, {%4,%5,%6,%7}, {%8,%9}, {%0,%1,%2,%3};" \
        : "+f"((C)[0]), "+f"((C)[1]), "+f"((C)[2]), "+f"((C)[3]) \
        : "r"((A)[0]), "r"((A)[1]), "r"((A)[2]), "r"((A)[3]), "r"(b0), "r"(b1))

// swizzled byte offset, 128B rows (64 halves)
__device__ __forceinline__ uint32_t swz1(int row, int kh) {
    return (uint32_t)(row * 128 + ((((kh >> 3) ^ (row & 7)) << 4)));
}
// swizzled byte offset, 256B rows (128 halves)
__device__ __forceinline__ uint32_t swz2(int row, int kh) {
    int c = kh >> 3;
    return (uint32_t)(row * 256 + ((((c & 8) | ((c ^ (row & 7)) & 7)) << 4)));
}

__device__ __forceinline__ uint2 round4(float4 v) {
    uint2 hw;
    hw.x = pk2(v.x, v.y);
    hw.y = pk2(v.z, v.w);
    return hw;
}

// ---------------------------------------------------------------------------
// Stage 1: partial[ks][m 128-tile][0..127] = X[m, kchunk] . feats^T (fp16 MMA)
// grid (16 m, 8 ks), 512 threads (16 warps, warp tile 32m x 32n).
// X and F both converted inline from fp32 (no prep kernel).
// smem per buffer (32768B): X +0 (16KB), F +16384 (16KB); two buffers = 64KB.
// Epilogue: fp16 partials, then PDL trigger.
// ---------------------------------------------------------------------------
__global__ __launch_bounds__(512, 1) void stage1(const float* __restrict__ A_,
                                                 const float* __restrict__ B_,
                                                 const float* __restrict__ F_) {
    extern __shared__ char smem[];
    const int t = threadIdx.x, lane = t & 31, wid = t >> 5;
    const uint32_t sb = su32(smem);
    const int m0 = blockIdx.x * 128;
    const int ks = blockIdx.y;
    const float* X = (m0 < NROW) ? A_ : B_;
    const int mb = (m0 < NROW) ? m0 : m0 - NROW;
    const int kbase = ks * KCHUNK;

    const int wy = wid & 3, wx = wid >> 2;
    const int m0w = wy * 32, n0w = wx * 32;
    const int aRow = lane & 15, aK = (lane >> 4) << 3;
    const int bN = ((lane >> 4) << 3) + (lane & 7), bK = ((lane >> 3) & 1) << 3;

    float acc[2][4][4];
    #pragma unroll
    for (int i = 0; i < 2; i++)
        #pragma unroll
        for (int j = 0; j < 4; j++)
            #pragma unroll
            for (int q = 0; q < 4; q++) acc[i][j][q] = 0.f;

    float xr[2][8], fr[2][8];

    // per-thread tile coords: 128 rows x 8 chunks = 1024 units / 512 thr
    int rows_[2], cs_[2];
    #pragma unroll
    for (int i = 0; i < 2; i++) {
        int idx = t + i * 512;
        rows_[i] = idx >> 3;
        cs_[i]   = idx & 7;
    }

    // ---- slab 0 prologue ----
    {
        const int kk = kbase;
        #pragma unroll
        for (int i = 0; i < 2; i++) {
            const float* sx = &X[(size_t)(mb + rows_[i]) * KDIM + kk + cs_[i] * 8];
            const float* sf = &F_[(size_t)rows_[i] * KDIM + kk + cs_[i] * 8];
            *(float4*)&xr[i][0] = *(const float4*)sx;
            *(float4*)&xr[i][4] = *(const float4*)(sx + 4);
            *(float4*)&fr[i][0] = *(const float4*)sf;
            *(float4*)&fr[i][4] = *(const float4*)(sf + 4);
        }
        #pragma unroll
        for (int i = 0; i < 2; i++) {
            uint32_t off = swz1(rows_[i], cs_[i] * 8);
            uint2 x0 = round4(*(float4*)&xr[i][0]);
            uint2 x1 = round4(*(float4*)&xr[i][4]);
            uint2 f0 = round4(*(float4*)&fr[i][0]);
            uint2 f1 = round4(*(float4*)&fr[i][4]);
            *(uint4*)(smem + off)         = make_uint4(x0.x, x0.y, x1.x, x1.y);
            *(uint4*)(smem + 16384 + off) = make_uint4(f0.x, f0.y, f1.x, f1.y);
        }
        __syncthreads();
    }

    // ---- main loop over 4 slabs ----
    #pragma unroll 1
    for (int s = 0; s < 4; s++) {
        const int p = s & 1, np = p ^ 1;
        if (s < 3) {
            const int kk = kbase + (s + 1) * BK;
            #pragma unroll
            for (int i = 0; i < 2; i++) {
                const float* sx = &X[(size_t)(mb + rows_[i]) * KDIM + kk + cs_[i] * 8];
                const float* sf = &F_[(size_t)rows_[i] * KDIM + kk + cs_[i] * 8];
                *(float4*)&xr[i][0] = *(const float4*)sx;
                *(float4*)&xr[i][4] = *(const float4*)(sx + 4);
                *(float4*)&fr[i][0] = *(const float4*)sf;
                *(float4*)&fr[i][4] = *(const float4*)(sf + 4);
            }
        }

        const uint32_t base = sb + p * 32768;
        #pragma unroll
        for (int k16 = 0; k16 < 4; k16++) {
            const int kh = k16 * 16;
            uint32_t ah[2][4], bh[2][4];
            #pragma unroll
            for (int mt = 0; mt < 2; mt++) {
                uint32_t ra = base + swz1(m0w + mt * 16 + aRow, kh + aK);
                LDSM4(ah[mt], ra);
            }
            #pragma unroll
            for (int g = 0; g < 2; g++) {
                uint32_t rb = base + 16384 + swz1(n0w + g * 16 + bN, kh + bK);
                LDSM4(bh[g], rb);
            }
            #pragma unroll
            for (int mt = 0; mt < 2; mt++)
                #pragma unroll
                for (int nt = 0; nt < 4; nt++) {
                    uint32_t h0 = bh[nt >> 1][(nt & 1) * 2], h1 = bh[nt >> 1][(nt & 1) * 2 + 1];
                    MMA(acc[mt][nt], ah[mt], h0, h1);
                }
        }

        if (s < 3) {
            const uint32_t nboff = (uint32_t)(np * 32768);
            #pragma unroll
            for (int i = 0; i < 2; i++) {
                uint32_t off = nboff + swz1(rows_[i], cs_[i] * 8);
                uint2 x0 = round4(*(float4*)&xr[i][0]);
                uint2 x1 = round4(*(float4*)&xr[i][4]);
                uint2 f0 = round4(*(float4*)&fr[i][0]);
                uint2 f1 = round4(*(float4*)&fr[i][4]);
                *(uint4*)(smem + off)         = make_uint4(x0.x, x0.y, x1.x, x1.y);
                *(uint4*)(smem + 16384 + off) = make_uint4(f0.x, f0.y, f1.x, f1.y);
            }
        }
        __syncthreads();
    }

    // ---- epilogue: write fp16 partials, then allow dependents ----
    __half* dst = g_ph + (size_t)ks * (2048 * NF);
    #pragma unroll
    for (int mt = 0; mt < 2; mt++)
        #pragma unroll
        for (int nt = 0; nt < 4; nt++) {
            int r = m0 + m0w + mt * 16 + (lane >> 2);
            int cc = n0w + nt * 8 + (lane & 3) * 2;
            *(uint32_t*)&dst[(size_t)r * NF + cc] =
                pk2(acc[mt][nt][0], acc[mt][nt][1]);
            *(uint32_t*)&dst[(size_t)(r + 8) * NF + cc] =
                pk2(acc[mt][nt][2], acc[mt][nt][3]);
        }
    gdc_launch();
}

// ---------------------------------------------------------------------------
// Reduce: sum fp16 split-K partials in fp32, relu, round to fp16. PDL both ends.
// ---------------------------------------------------------------------------
__global__ void reduce_relu() {
    int g = blockIdx.x * blockDim.x + threadIdx.x;   // 65536 threads
    size_t o = (size_t)g * 4;
    gdc_wait();                                      // g_ph ready
    float4 s = make_float4(0.f, 0.f, 0.f, 0.f);
    #pragma unroll
    for (int p = 0; p < SPLITK; p++) {
        uint2 v = *(const uint2*)&g_ph[(size_t)p * (2048 * NF) + o];
        __half2 h0 = *reinterpret_cast<__half2*>(&v.x);
        __half2 h1 = *reinterpret_cast<__half2*>(&v.y);
        float2 f0 = __half22float2(h0);
        float2 f1 = __half22float2(h1);
        s.x += f0.x; s.y += f0.y; s.z += f1.x; s.w += f1.y;
    }
    s.x = fmaxf(s.x, 0.f); s.y = fmaxf(s.y, 0.f);
    s.z = fmaxf(s.z, 0.f); s.w = fmaxf(s.w, 0.f);
    *(uint2*)&g_shi[o] = round4(s);
    gdc_launch();
}

// ---------------------------------------------------------------------------
// Stage 2: out[i][j] = sum_k shi[i][k] * shi[1024+j][k]
// grid (16 j, 8 i): CTA 128i x 64j, 512 threads (warp tile 32i x 16j).
// smem: AHI +0 (32KB), BHI +32768 (16KB) = 48KB, cp.async 2 K-half groups.
// PDL wait before loads.
// ---------------------------------------------------------------------------
__global__ __launch_bounds__(512, 1) void stage2(float* __restrict__ out) {
    extern __shared__ char smem[];
    const uint32_t sb = su32(smem);
    const int t = threadIdx.x, lane = t & 31, wid = t >> 5;
    const int it = blockIdx.y * 128, jt = blockIdx.x * 64;
    const int wy = wid & 3, wx = wid >> 2;
    const int m0w = wy * 32, n0w = wx * 16;

    gdc_wait();                                      // g_shi ready

    // two K-half commit groups: group cc covers kh [cc*64, cc*64+64)
    #pragma unroll
    for (int cc = 0; cc < 2; cc++) {
        #pragma unroll
        for (int i = 0; i < 2; i++) {
            int idx = t + i * 512;                 // 0..1023
            int row = idx >> 3, c = (idx & 7) + cc * 8;
            uint32_t off = swz2(row, c * 8);
            cp16(sb + off, &g_shi[(size_t)(it + row) * NF + c * 8]);
        }
        {
            int row = t >> 3, c = (t & 7) + cc * 8;   // 512 -> 64 rows
            uint32_t off = swz2(row, c * 8);
            cp16(sb + 32768 + off, &g_shi[(size_t)(1024 + jt + row) * NF + c * 8]);
        }
        CP_COMMIT();
    }

    const int aRow = lane & 15, aK = (lane >> 4) << 3;
    const int bN = ((lane >> 4) << 3) + (lane & 7), bK = ((lane >> 3) & 1) << 3;

    float acc[2][2][4];
    #pragma unroll
    for (int i = 0; i < 2; i++)
        #pragma unroll
        for (int j = 0; j < 2; j++)
            #pragma unroll
            for (int q = 0; q < 4; q++) acc[i][j][q] = 0.f;

    CP_WAIT1();
    __syncthreads();

    #pragma unroll
    for (int half = 0; half < 2; half++) {
        #pragma unroll
        for (int k16 = 0; k16 < 4; k16++) {
            const int kh = half * 64 + k16 * 16;
            uint32_t ah[2][4], bh[4];
            #pragma unroll
            for (int mt = 0; mt < 2; mt++) {
                uint32_t ra = sb + swz2(m0w + mt * 16 + aRow, kh + aK);
                LDSM4(ah[mt], ra);
            }
            {
                uint32_t rb = sb + 32768 + swz2(n0w + bN, kh + bK);
                LDSM4(bh, rb);
            }
            #pragma unroll
            for (int mt = 0; mt < 2; mt++)
                #pragma unroll
                for (int nt = 0; nt < 2; nt++) {
                    uint32_t h0 = bh[nt * 2], h1 = bh[nt * 2 + 1];
                    MMA(acc[mt][nt], ah[mt], h0, h1);
                }
        }
        if (half == 0) {
            CP_WAIT0();
            __syncthreads();
        }
    }

    #pragma unroll
    for (int mt = 0; mt < 2; mt++)
        #pragma unroll
        for (int nt = 0; nt < 2; nt++) {
            int r = it + m0w + mt * 16 + (lane >> 2);
            int cc = jt + n0w + nt * 8 + (lane & 3) * 2;
            *(float2*)&out[(size_t)r * NROW + cc] =
                make_float2(acc[mt][nt][0], acc[mt][nt][1]);
            *(float2*)&out[(size_t)(r + 8) * NROW + cc] =
                make_float2(acc[mt][nt][2], acc[mt][nt][3]);
        }
}

// ---------------------------------------------------------------------------
extern "C" void kernel_launch(void* const* d_in, const int* in_sizes, int n_in,
                              void* d_out, int out_size) {
    (void)in_sizes; (void)n_in; (void)out_size;
    const float* a = (const float*)d_in[0];
    const float* b = (const float*)d_in[1];
    const float* f = (const float*)d_in[2];
    float* out = (float*)d_out;

    cudaFuncSetAttribute(stage1, cudaFuncAttributeMaxDynamicSharedMemorySize, 65536);
    cudaFuncSetAttribute(stage2, cudaFuncAttributeMaxDynamicSharedMemorySize, 49152);

    // stage1: normal launch
    stage1<<<dim3(16, SPLITK), 512, 65536>>>(a, b, f);

    // reduce: PDL-chained to stage1
    {
        cudaLaunchConfig_t cfg = {};
        cfg.gridDim = dim3(256);
        cfg.blockDim = dim3(256);
        cfg.dynamicSmemBytes = 0;
        cfg.stream = 0;
        cudaLaunchAttribute at[1];
        at[0].id = cudaLaunchAttributeProgrammaticStreamSerialization;
        at[0].val.programmaticStreamSerializationAllowed = 1;
        cfg.attrs = at;
        cfg.numAttrs = 1;
        cudaLaunchKernelEx(&cfg, reduce_relu);
    }

    // stage2: PDL-chained to reduce
    {
        cudaLaunchConfig_t cfg = {};
        cfg.gridDim = dim3(16, 8);
        cfg.blockDim = dim3(512);
        cfg.dynamicSmemBytes = 49152;
        cfg.stream = 0;
        cudaLaunchAttribute at[1];
        at[0].id = cudaLaunchAttributeProgrammaticStreamSerialization;
        at[0].val.programmaticStreamSerializationAllowed = 1;
        cfg.attrs = at;
        cfg.numAttrs = 1;
        cudaLaunchKernelEx(&cfg, stage2, out);
    }
}

// round 16
// speedup vs baseline: 1.1193x; 1.0133x over previous
#include <cuda_runtime.h>
#include <cuda_fp16.h>
#include <cstdint>

#define NROW 1024
#define KDIM 2048
#define NF   128
#define SPLITK 8
#define KCHUNK (KDIM / SPLITK)   // 256
#define BK 64

// ---------------------------------------------------------------------------
// Device scratch
// ---------------------------------------------------------------------------
__device__ __half g_ph[SPLITK * 2048 * NF];      // fp16 split-K partials [ks][m][n]
__device__ __half g_shi[2048 * NF];              // relu(scores) fp16, [m][k]

// ---------------------------------------------------------------------------
// Helpers
// ---------------------------------------------------------------------------
__device__ __forceinline__ uint32_t su32(const void* p) {
    return (uint32_t)__cvta_generic_to_shared(p);
}
__device__ __forceinline__ uint32_t pk2(float a, float b) {
    __half2 h = __floats2half2_rn(a, b);          // packed cvt.rn.f16x2.f32
    return *reinterpret_cast<uint32_t*>(&h);
}
__device__ __forceinline__ void cp16(uint32_t dst, const void* src) {
    asm volatile("cp.async.ca.shared.global [%0], [%1], 16;" :: "r"(dst), "l"(src));
}

#define CP_COMMIT() asm volatile("cp.async.commit_group;" ::: "memory")
#define CP_WAIT0()  asm volatile("cp.async.wait_group 0;"  ::: "memory")

#define LDSM4(R, addr) \
    asm volatile("ldmatrix.sync.aligned.m8n8.x4.shared.b16 {%0,%1,%2,%3}, [%4];" \
        : "=r"((R)[0]), "=r"((R)[1]), "=r"((R)[2]), "=r"((R)[3]) : "r"(addr))

#define MMA(C, A, b0, b1) \
    asm volatile("mma.sync.aligned.m16n8k16.row.col.f32.f16.f16.f32 " \
        "{%0,%1,%2,%3}, {%4,%5,%6,%7}, {%8,%9}, {%0,%1,%2,%3};" \
        : "+f"((C)[0]), "+f"((C)[1]), "+f"((C)[2]), "+f"((C)[3]) \
        : "r"((A)[0]), "r"((A)[1]), "r"((A)[2]), "r"((A)[3]), "r"(b0), "r"(b1))

// swizzled byte offset, 128B rows (64 halves)
__device__ __forceinline__ uint32_t swz1(int row, int kh) {
    return (uint32_t)(row * 128 + ((((kh >> 3) ^ (row & 7)) << 4)));
}
// swizzled byte offset, 256B rows (128 halves)
__device__ __forceinline__ uint32_t swz2(int row, int kh) {
    int c = kh >> 3;
    return (uint32_t)(row * 256 + ((((c & 8) | ((c ^ (row & 7)) & 7)) << 4)));
}

__device__ __forceinline__ uint2 round4(float4 v) {
    uint2 hw;
    hw.x = pk2(v.x, v.y);
    hw.y = pk2(v.z, v.w);
    return hw;
}

// ---------------------------------------------------------------------------
// Stage 1: partial[ks][m 128-tile][0..127] = X[m, kchunk] . feats^T (fp16 MMA)
// grid (16 m, 8 ks), 512 threads (16 warps, warp tile 32m x 32n).
// X and F both converted inline from fp32 (no prep kernel).
// smem per buffer (32768B): X +0 (16KB), F +16384 (16KB); two buffers = 64KB.
// Epilogue: fp16 partials.
// ---------------------------------------------------------------------------
__global__ __launch_bounds__(512, 1) void stage1(const float* __restrict__ A_,
                                                 const float* __restrict__ B_,
                                                 const float* __restrict__ F_) {
    extern __shared__ char smem[];
    const int t = threadIdx.x, lane = t & 31, wid = t >> 5;
    const uint32_t sb = su32(smem);
    const int m0 = blockIdx.x * 128;
    const int ks = blockIdx.y;
    const float* X = (m0 < NROW) ? A_ : B_;
    const int mb = (m0 < NROW) ? m0 : m0 - NROW;
    const int kbase = ks * KCHUNK;

    const int wy = wid & 3, wx = wid >> 2;
    const int m0w = wy * 32, n0w = wx * 32;
    const int aRow = lane & 15, aK = (lane >> 4) << 3;
    const int bN = ((lane >> 4) << 3) + (lane & 7), bK = ((lane >> 3) & 1) << 3;

    float acc[2][4][4];
    #pragma unroll
    for (int i = 0; i < 2; i++)
        #pragma unroll
        for (int j = 0; j < 4; j++)
            #pragma unroll
            for (int q = 0; q < 4; q++) acc[i][j][q] = 0.f;

    float xr[2][8], fr[2][8];

    // per-thread tile coords: 128 rows x 8 chunks = 1024 units / 512 thr
    int rows_[2], cs_[2];
    #pragma unroll
    for (int i = 0; i < 2; i++) {
        int idx = t + i * 512;
        rows_[i] = idx >> 3;
        cs_[i]   = idx & 7;
    }

    // ---- slab 0 prologue ----
    {
        const int kk = kbase;
        #pragma unroll
        for (int i = 0; i < 2; i++) {
            const float* sx = &X[(size_t)(mb + rows_[i]) * KDIM + kk + cs_[i] * 8];
            const float* sf = &F_[(size_t)rows_[i] * KDIM + kk + cs_[i] * 8];
            *(float4*)&xr[i][0] = *(const float4*)sx;
            *(float4*)&xr[i][4] = *(const float4*)(sx + 4);
            *(float4*)&fr[i][0] = *(const float4*)sf;
            *(float4*)&fr[i][4] = *(const float4*)(sf + 4);
        }
        #pragma unroll
        for (int i = 0; i < 2; i++) {
            uint32_t off = swz1(rows_[i], cs_[i] * 8);
            uint2 x0 = round4(*(float4*)&xr[i][0]);
            uint2 x1 = round4(*(float4*)&xr[i][4]);
            uint2 f0 = round4(*(float4*)&fr[i][0]);
            uint2 f1 = round4(*(float4*)&fr[i][4]);
            *(uint4*)(smem + off)         = make_uint4(x0.x, x0.y, x1.x, x1.y);
            *(uint4*)(smem + 16384 + off) = make_uint4(f0.x, f0.y, f1.x, f1.y);
        }
        __syncthreads();
    }

    // ---- main loop over 4 slabs ----
    #pragma unroll 1
    for (int s = 0; s < 4; s++) {
        const int p = s & 1, np = p ^ 1;
        if (s < 3) {
            const int kk = kbase + (s + 1) * BK;
            #pragma unroll
            for (int i = 0; i < 2; i++) {
                const float* sx = &X[(size_t)(mb + rows_[i]) * KDIM + kk + cs_[i] * 8];
                const float* sf = &F_[(size_t)rows_[i] * KDIM + kk + cs_[i] * 8];
                *(float4*)&xr[i][0] = *(const float4*)sx;
                *(float4*)&xr[i][4] = *(const float4*)(sx + 4);
                *(float4*)&fr[i][0] = *(const float4*)sf;
                *(float4*)&fr[i][4] = *(const float4*)(sf + 4);
            }
        }

        const uint32_t base = sb + p * 32768;
        #pragma unroll
        for (int k16 = 0; k16 < 4; k16++) {
            const int kh = k16 * 16;
            uint32_t ah[2][4], bh[2][4];
            #pragma unroll
            for (int mt = 0; mt < 2; mt++) {
                uint32_t ra = base + swz1(m0w + mt * 16 + aRow, kh + aK);
                LDSM4(ah[mt], ra);
            }
            #pragma unroll
            for (int g = 0; g < 2; g++) {
                uint32_t rb = base + 16384 + swz1(n0w + g * 16 + bN, kh + bK);
                LDSM4(bh[g], rb);
            }
            #pragma unroll
            for (int mt = 0; mt < 2; mt++)
                #pragma unroll
                for (int nt = 0; nt < 4; nt++) {
                    uint32_t h0 = bh[nt >> 1][(nt & 1) * 2], h1 = bh[nt >> 1][(nt & 1) * 2 + 1];
                    MMA(acc[mt][nt], ah[mt], h0, h1);
                }
        }

        if (s < 3) {
            const uint32_t nboff = (uint32_t)(np * 32768);
            #pragma unroll
            for (int i = 0; i < 2; i++) {
                uint32_t off = nboff + swz1(rows_[i], cs_[i] * 8);
                uint2 x0 = round4(*(float4*)&xr[i][0]);
                uint2 x1 = round4(*(float4*)&xr[i][4]);
                uint2 f0 = round4(*(float4*)&fr[i][0]);
                uint2 f1 = round4(*(float4*)&fr[i][4]);
                *(uint4*)(smem + off)         = make_uint4(x0.x, x0.y, x1.x, x1.y);
                *(uint4*)(smem + 16384 + off) = make_uint4(f0.x, f0.y, f1.x, f1.y);
            }
        }
        __syncthreads();
    }

    // ---- epilogue: write fp16 partials ----
    __half* dst = g_ph + (size_t)ks * (2048 * NF);
    #pragma unroll
    for (int mt = 0; mt < 2; mt++)
        #pragma unroll
        for (int nt = 0; nt < 4; nt++) {
            int r = m0 + m0w + mt * 16 + (lane >> 2);
            int cc = n0w + nt * 8 + (lane & 3) * 2;
            *(uint32_t*)&dst[(size_t)r * NF + cc] =
                pk2(acc[mt][nt][0], acc[mt][nt][1]);
            *(uint32_t*)&dst[(size_t)(r + 8) * NF + cc] =
                pk2(acc[mt][nt][2], acc[mt][nt][3]);
        }
}

// ---------------------------------------------------------------------------
// Reduce: sum fp16 split-K partials in fp32, relu, round to fp16
// ---------------------------------------------------------------------------
__global__ void reduce_relu() {
    int g = blockIdx.x * blockDim.x + threadIdx.x;   // 65536 threads
    size_t o = (size_t)g * 4;
    float4 s = make_float4(0.f, 0.f, 0.f, 0.f);
    #pragma unroll
    for (int p = 0; p < SPLITK; p++) {
        uint2 v = *(const uint2*)&g_ph[(size_t)p * (2048 * NF) + o];
        __half2 h0 = *reinterpret_cast<__half2*>(&v.x);
        __half2 h1 = *reinterpret_cast<__half2*>(&v.y);
        float2 f0 = __half22float2(h0);
        float2 f1 = __half22float2(h1);
        s.x += f0.x; s.y += f0.y; s.z += f1.x; s.w += f1.y;
    }
    s.x = fmaxf(s.x, 0.f); s.y = fmaxf(s.y, 0.f);
    s.z = fmaxf(s.z, 0.f); s.w = fmaxf(s.w, 0.f);
    *(uint2*)&g_shi[o] = round4(s);
}

// ---------------------------------------------------------------------------
// Stage 2: out[i][j] = sum_k shi[i][k] * shi[1024+j][k]
// grid (16 j, 8 i): CTA 128i x 64j, 512 threads (warp tile 32i x 16j).
// smem: AHI +0 (32KB), BHI +32768 (16KB) = 48KB.
// 4-deep cp.async pipeline over K=32 chunks: all groups issued up front,
// compute chunk c after wait_group(3-c).
// ---------------------------------------------------------------------------
__global__ __launch_bounds__(512, 1) void stage2(float* __restrict__ out) {
    extern __shared__ char smem[];
    const uint32_t sb = su32(smem);
    const int t = threadIdx.x, lane = t & 31, wid = t >> 5;
    const int it = blockIdx.y * 128, jt = blockIdx.x * 64;
    const int wy = wid & 3, wx = wid >> 2;
    const int m0w = wy * 32, n0w = wx * 16;

    // 4 commit groups, each covering K-chunk [cc*32, cc*32+32)
    // A: 128 rows x 4 units/chunk = 512 cp16 per chunk (1 per thread)
    // B: 64 rows x 4 units/chunk = 256 cp16 per chunk (half the threads)
    {
        const int rowA = t >> 2;                     // 0..127
        const int uA   = t & 3;                      // unit within chunk
        const int rowB = (t & 255) >> 2;             // 0..63
        const int uB   = t & 3;
        const bool doB = (t < 256);
        const size_t ra = (size_t)(it + rowA) * NF;
        const size_t rb = (size_t)(1024 + jt + rowB) * NF;
        #pragma unroll
        for (int cc = 0; cc < 4; cc++) {
            int ua = uA + cc * 4;                    // 8-half unit 0..15
            cp16(sb + swz2(rowA, ua * 8), &g_shi[ra + ua * 8]);
            if (doB) {
                int ub = uB + cc * 4;
                cp16(sb + 32768 + swz2(rowB, ub * 8), &g_shi[rb + ub * 8]);
            }
            CP_COMMIT();
        }
    }

    const int aRow = lane & 15, aK = (lane >> 4) << 3;
    const int bN = ((lane >> 4) << 3) + (lane & 7), bK = ((lane >> 3) & 1) << 3;

    float acc[2][2][4];
    #pragma unroll
    for (int i = 0; i < 2; i++)
        #pragma unroll
        for (int j = 0; j < 2; j++)
            #pragma unroll
            for (int q = 0; q < 4; q++) acc[i][j][q] = 0.f;

    #pragma unroll
    for (int cc = 0; cc < 4; cc++) {
        if (cc == 0)      asm volatile("cp.async.wait_group 3;" ::: "memory");
        else if (cc == 1) asm volatile("cp.async.wait_group 2;" ::: "memory");
        else if (cc == 2) asm volatile("cp.async.wait_group 1;" ::: "memory");
        else              asm volatile("cp.async.wait_group 0;" ::: "memory");
        __syncthreads();

        #pragma unroll
        for (int k16 = 0; k16 < 2; k16++) {
            const int kh = cc * 32 + k16 * 16;
            uint32_t ah[2][4], bh[4];
            #pragma unroll
            for (int mt = 0; mt < 2; mt++) {
                uint32_t ra = sb + swz2(m0w + mt * 16 + aRow, kh + aK);
                LDSM4(ah[mt], ra);
            }
            {
                uint32_t rb = sb + 32768 + swz2(n0w + bN, kh + bK);
                LDSM4(bh, rb);
            }
            #pragma unroll
            for (int mt = 0; mt < 2; mt++)
                #pragma unroll
                for (int nt = 0; nt < 2; nt++) {
                    uint32_t h0 = bh[nt * 2], h1 = bh[nt * 2 + 1];
                    MMA(acc[mt][nt], ah[mt], h0, h1);
                }
        }
    }

    #pragma unroll
    for (int mt = 0; mt < 2; mt++)
        #pragma unroll
        for (int nt = 0; nt < 2; nt++) {
            int r = it + m0w + mt * 16 + (lane >> 2);
            int cc = jt + n0w + nt * 8 + (lane & 3) * 2;
            *(float2*)&out[(size_t)r * NROW + cc] =
                make_float2(acc[mt][nt][0], acc[mt][nt][1]);
            *(float2*)&out[(size_t)(r + 8) * NROW + cc] =
                make_float2(acc[mt][nt][2], acc[mt][nt][3]);
        }
}

// ---------------------------------------------------------------------------
extern "C" void kernel_launch(void* const* d_in, const int* in_sizes, int n_in,
                              void* d_out, int out_size) {
    (void)in_sizes; (void)n_in; (void)out_size;
    const float* a = (const float*)d_in[0];
    const float* b = (const float*)d_in[1];
    const float* f = (const float*)d_in[2];
    float* out = (float*)d_out;

    cudaFuncSetAttribute(stage1, cudaFuncAttributeMaxDynamicSharedMemorySize, 65536);
    cudaFuncSetAttribute(stage2, cudaFuncAttributeMaxDynamicSharedMemorySize, 49152);

    stage1<<<dim3(16, SPLITK), 512, 65536>>>(a, b, f);
    reduce_relu<<<128, 512>>>();
    stage2<<<dim3(16, 8), 512, 49152>>>(out);
}